// round 7
// baseline (speedup 1.0000x reference)
#include <cuda_runtime.h>
#include <math.h>
#include <stdint.h>

#define S_ 4
#define K_ 50
#define T_ 25
#define R_ 128
#define V_ 10000
#define TH_ 800
#define EH_ 200
#define B_ 128
#define VK_ (V_ + K_)
#define GATE_ (4 * EH_)    /* 800 */
#define INP_  (EH_ + K_)   /* 250 */
#define INP4_ 64           /* padded input quads: 64*4 = 256 >= 250 */
#define EH4_  (EH_ / 4)    /* 50 */
#define NB_   8            /* gate blocks in the scan */
#define UPB_  (EH_ / NB_)  /* 25 units per gate block */
#define ROWS_ (4 * UPB_)   /* 100 gate rows per block */
#define LOG_DELTA (-5.2983173665480363f) /* log(0.005) */

// ---------------- scratch (static device globals; no allocation) -------------
__device__ float g_xemb[T_ * EH_];
__device__ float g_etas[T_ * K_];
__device__ float g_hs[T_ * EH_];           // published h_t
__device__ float g_A1[B_ * VK_];
__device__ float g_h1[B_ * TH_];
__device__ float g_h2[B_ * TH_];
__device__ float g_muth[B_ * K_];
__device__ float g_lsth[B_ * K_];
__device__ float g_theta[B_ * K_];
__device__ float g_alpha0[T_ * K_ * R_];
__device__ float g_beta[(size_t)T_ * K_ * V_];   // 50 MB
// scan weight slices
__device__ float4 g_Wg4[NB_ * EH4_ * ROWS_];  // per gate-block: [i4][row], 80 KB/block
__device__ float4 g_muWT4[INP4_ * K_];        // [64][50], zero-padded i
__device__ float4 g_lsWT4[INP4_ * K_];
__device__ float g_biasc[GATE_];
__device__ float g_Gx[T_ * GATE_];            // x-part of gates, all t
__device__ volatile int g_syncv;              // scan step barrier counter
// stats: 0=kl_alpha 1=kl_eta 2=nll_raw 3=klth_raw 4=ld_p0 5..8=d_p0 9=ld_pt 10..13=d_pt
__device__ float g_stats[16];

// ---------------- helpers ----------------------------------------------------
__device__ __forceinline__ float sigmoidf_(float x) { return 1.0f / (1.0f + expf(-x)); }

__device__ __forceinline__ float blockReduceSum256(float v, float* sh) {
    int tid = threadIdx.x;
    sh[tid] = v;
    __syncthreads();
    for (int s = blockDim.x >> 1; s > 0; s >>= 1) {
        if (tid < s) sh[tid] += sh[tid + s];
        __syncthreads();
    }
    return sh[0];
}

__device__ double logabsdet4(double M[4][4]) {
    double ld = 0.0;
    for (int i = 0; i < 4; i++) {
        int p = i; double best = fabs(M[i][i]);
        for (int r = i + 1; r < 4; r++)
            if (fabs(M[r][i]) > best) { best = fabs(M[r][i]); p = r; }
        if (p != i)
            for (int c = 0; c < 4; c++) { double t = M[i][c]; M[i][c] = M[p][c]; M[p][c] = t; }
        ld += log(fabs(M[i][i]));
        for (int r = i + 1; r < 4; r++) {
            double f = M[r][i] / M[i][i];
            for (int c = i; c < 4; c++) M[r][c] -= f * M[i][c];
        }
    }
    return ld;
}

// ---------------- kernels ----------------------------------------------------
__global__ void init_kernel() {
    int t = threadIdx.x;
    if (t == 0 || t == 2 || t == 3) g_stats[t] = 0.0f;  // atomic accumulators
    if (t == 4) g_syncv = 0;                            // scan barrier reset
}

__global__ void prep_prior_kernel(const float* __restrict__ src) {
    double M0[4][4], Mt[4][4];
    for (int i = 0; i < 4; i++)
        for (int j = 0; j < 4; j++) {
            double v = (double)src[i * 4 + j];
            M0[i][j] = exp(v);
            Mt[i][j] = 0.005 * v;
        }
    for (int i = 0; i < 4; i++) {
        g_stats[5 + i]  = (float)M0[i][i];
        g_stats[10 + i] = (float)Mt[i][i];
    }
    g_stats[4] = (float)logabsdet4(M0);
    g_stats[9] = (float)logabsdet4(Mt);
}

// pack per-block Whh slices + transposed eta weights + combined bias
__global__ void prep_lstm_kernel(const float* __restrict__ Whh,
                                 const float* __restrict__ muW, const float* __restrict__ lsW,
                                 const float* __restrict__ bih, const float* __restrict__ bhh) {
    int idx = blockIdx.x * blockDim.x + threadIdx.x;
    if (idx < NB_ * EH4_ * ROWS_) {
        int j  = idx / (EH4_ * ROWS_);
        int rem = idx % (EH4_ * ROWS_);
        int i4 = rem / ROWS_;
        int r  = rem % ROWS_;
        int q  = r / UPB_, ul = r % UPB_;
        int grow = q * EH_ + j * UPB_ + ul;            // global gate row
        const float* w = Whh + (size_t)grow * EH_ + 4 * i4;
        g_Wg4[idx] = make_float4(w[0], w[1], w[2], w[3]);
    }
    if (idx < INP4_ * K_) {
        int i4 = idx / K_, k = idx % K_;
        float4 m, l;
        float* mp = (float*)&m;
        float* lp = (float*)&l;
        for (int jj = 0; jj < 4; jj++) {
            int i = 4 * i4 + jj;
            mp[jj] = (i < INP_) ? muW[(size_t)k * INP_ + i] : 0.0f;
            lp[jj] = (i < INP_) ? lsW[(size_t)k * INP_ + i] : 0.0f;
        }
        g_muWT4[idx] = m;
        g_lsWT4[idx] = l;
    }
    if (idx < GATE_) g_biasc[idx] = bih[idx] + bhh[idx];
}

__global__ void kl_alpha_kernel(const float* __restrict__ mu, const float* __restrict__ lsig) {
    __shared__ float sh[256];
    int idx = blockIdx.x * blockDim.x + threadIdx.x;
    float val = 0.0f;
    if (idx < K_ * T_ * R_) {
        int r = idx % R_;
        int t = (idx / R_) % T_;
        int k = idx / (R_ * T_);
        float ldp = (t == 0) ? g_stats[4] : g_stats[9];
        const float* dp = (t == 0) ? &g_stats[5] : &g_stats[10];
        float acc = -ldp - (float)S_;
        for (int s = 0; s < S_; s++) {
            size_t off = ((size_t)(s * K_ + k) * T_ + t) * R_ + r;
            float lsv = lsig[off];
            float invq = expf(-lsv);
            float m = mu[off];
            float dmu = (t == 0) ? m : (m - mu[off - R_]);
            acc += lsv + dp[s] * invq + dmu * dmu * invq;
        }
        val = acc;
    }
    float tot = blockReduceSum256(val, sh);
    if (threadIdx.x == 0) atomicAdd(&g_stats[0], tot);
}

// x_emb[t][e] = rnn_inp[t] . eta_map_W[e] + b[e]   (warp per output, float4)
__global__ void xemb_kernel(const float* __restrict__ rnn, const float* __restrict__ W,
                            const float* __restrict__ b) {
    int gw = (blockIdx.x * blockDim.x + threadIdx.x) >> 5;
    int lane = threadIdx.x & 31;
    if (gw >= T_ * EH_) return;
    int t = gw / EH_, e = gw % EH_;
    const float4* x = (const float4*)(rnn + (size_t)t * V_);
    const float4* w = (const float4*)(W + (size_t)e * V_);
    float acc = 0.0f;
    for (int v = lane; v < V_ / 4; v += 32) {
        float4 a = x[v], c = w[v];
        acc += a.x * c.x + a.y * c.y + a.z * c.z + a.w * c.w;
    }
    for (int o = 16; o > 0; o >>= 1) acc += __shfl_down_sync(0xffffffffu, acc, o);
    if (lane == 0) g_xemb[t * EH_ + e] = acc + b[e];
}

// Multi-block sequential scan: 8 gate blocks (25 LSTM units each, 80 KB
// L1-resident weight slice) + 1 eta block, synchronized per timestep through
// a monotonically increasing global counter. 9 blocks always co-resident.
__global__ void scan_kernel(const float* __restrict__ mub, const float* __restrict__ lsb) {
    int j = blockIdx.x;
    int tid = threadIdx.x;
    if (j < NB_) {
        __shared__ float hvec[EH_];
        __shared__ float gloc[ROWS_];
        __shared__ float cst[UPB_];
        if (tid < UPB_) cst[tid] = 0.0f;
        __syncthreads();
        for (int t = 0; t < T_; t++) {
            if (t > 0) {
                if (tid == 0) { while (g_syncv < NB_ * t) { } }
                __syncthreads();
                __threadfence();
                for (int i = tid; i < EH_; i += 128)
                    hvec[i] = __ldcg(&g_hs[(t - 1) * EH_ + i]);
                __syncthreads();
            }
            if (tid < ROWS_) {
                float acc = 0.0f;
                if (t > 0) {
                    const float4* w = g_Wg4 + (size_t)j * EH4_ * ROWS_ + tid;
                    float a0 = 0, a1 = 0, a2 = 0, a3 = 0;
                    #pragma unroll 10
                    for (int i4 = 0; i4 < EH4_; i4++) {
                        float4 q = w[i4 * ROWS_];
                        a0 += q.x * hvec[4 * i4 + 0];
                        a1 += q.y * hvec[4 * i4 + 1];
                        a2 += q.z * hvec[4 * i4 + 2];
                        a3 += q.w * hvec[4 * i4 + 3];
                    }
                    acc = (a0 + a1) + (a2 + a3);
                }
                int q = tid / UPB_, ul = tid % UPB_;
                gloc[tid] = acc + g_Gx[t * GATE_ + q * EH_ + j * UPB_ + ul];
            }
            __syncthreads();
            if (tid < UPB_) {
                float ig = sigmoidf_(gloc[tid]);
                float fg = sigmoidf_(gloc[UPB_ + tid]);
                float gg = tanhf(gloc[2 * UPB_ + tid]);
                float og = sigmoidf_(gloc[3 * UPB_ + tid]);
                float c = fg * cst[tid] + ig * gg;
                cst[tid] = c;
                g_hs[t * EH_ + j * UPB_ + tid] = og * tanhf(c);
            }
            __threadfence();
            __syncthreads();
            if (tid == 0) atomicAdd((int*)&g_syncv, 1);
        }
    } else {
        // ---- eta block ----
        __shared__ float inp[4 * INP4_];   // [0..199]=h_t, [200..249]=eta_prev, rest 0
        __shared__ float newmu[K_], klk[K_];
        for (int i = tid; i < 4 * INP4_; i += 128) inp[i] = 0.0f;
        __syncthreads();
        float klacc = 0.0f;
        for (int t = 0; t < T_; t++) {
            if (tid == 0) { while (g_syncv < NB_ * (t + 1)) { } }
            __syncthreads();
            __threadfence();
            for (int i = tid; i < EH_; i += 128)
                inp[i] = __ldcg(&g_hs[t * EH_ + i]);
            __syncthreads();
            if (tid < K_) {
                float m0 = 0, m1 = 0, l0 = 0, l1 = 0;
                const float4* wm = g_muWT4 + tid;
                const float4* wl = g_lsWT4 + tid;
                #pragma unroll 8
                for (int i4 = 0; i4 < INP4_; i4++) {
                    float4 a = wm[i4 * K_];
                    float4 bq = wl[i4 * K_];
                    float x0 = inp[4 * i4 + 0], x1 = inp[4 * i4 + 1];
                    float x2 = inp[4 * i4 + 2], x3 = inp[4 * i4 + 3];
                    m0 += a.x * x0 + a.y * x1;
                    m1 += a.z * x2 + a.w * x3;
                    l0 += bq.x * x0 + bq.y * x1;
                    l1 += bq.z * x2 + bq.w * x3;
                }
                float m = mub[tid] + m0 + m1;
                float l = lsb[tid] + l0 + l1;
                float pls = (t == 0) ? 0.0f : LOG_DELTA;
                float denom = expf(pls) + 1e-6f;
                float ep = inp[EH_ + tid];
                float d = m - ep;
                klk[tid] = 0.5f * ((expf(l) + d * d) / denom - 1.0f + pls - l);
                newmu[tid] = m;
                g_etas[t * K_ + tid] = m;
            }
            __syncthreads();
            if (tid < K_) inp[EH_ + tid] = newmu[tid];
            if (tid == 0) { float s = 0.0f; for (int k = 0; k < K_; k++) s += klk[k]; klacc += s; }
            __syncthreads();
        }
        if (tid == 0) g_stats[1] = klacc;
    }
}

__global__ void build_A1_kernel(const float* __restrict__ nb, const int* __restrict__ times) {
    int idx = blockIdx.x * blockDim.x + threadIdx.x;
    if (idx >= B_ * VK_) return;
    int b = idx / VK_, j = idx % VK_;
    g_A1[idx] = (j < V_) ? nb[(size_t)b * V_ + j] : g_etas[times[b] * K_ + (j - V_)];
}

__global__ void build_alpha0_kernel(const float* __restrict__ mu) {
    int idx = blockIdx.x * blockDim.x + threadIdx.x;
    if (idx >= T_ * K_ * R_) return;
    int r = idx % R_;
    int k = (idx / R_) % K_;
    int t = idx / (R_ * K_);
    g_alpha0[idx] = mu[((size_t)k * T_ + t) * R_ + r];  // s=0 slice
}

// C[M,N] = act(A[M,Kd] * B[N,Kd]^T + bias)
template <int BM, int BN, int BK, int TM, int TN>
__global__ void sgemm_tn(const float* __restrict__ A, const float* __restrict__ Bm,
                         const float* __restrict__ bias, float* __restrict__ C,
                         int M, int N, int Kd, int act) {
    constexpr int TX = BN / TN;
    constexpr int TY = BM / TM;
    constexpr int NT = TX * TY;
    __shared__ float As[BK][BM + 1];
    __shared__ float Bs[BK][BN + 1];
    int tid = threadIdx.x;
    int tx = tid % TX, ty = tid / TX;
    int row0 = blockIdx.y * BM, col0 = blockIdx.x * BN;
    float acc[TM][TN];
    #pragma unroll
    for (int i = 0; i < TM; i++)
        #pragma unroll
        for (int j = 0; j < TN; j++) acc[i][j] = 0.0f;
    for (int k0 = 0; k0 < Kd; k0 += BK) {
        for (int i = tid; i < BM * BK; i += NT) {
            int m = i / BK, kk = i % BK;
            int gm = row0 + m, gk = k0 + kk;
            As[kk][m] = (gm < M && gk < Kd) ? A[(size_t)gm * Kd + gk] : 0.0f;
        }
        for (int i = tid; i < BN * BK; i += NT) {
            int n = i / BK, kk = i % BK;
            int gn = col0 + n, gk = k0 + kk;
            Bs[kk][n] = (gn < N && gk < Kd) ? Bm[(size_t)gn * Kd + gk] : 0.0f;
        }
        __syncthreads();
        #pragma unroll
        for (int kk = 0; kk < BK; kk++) {
            float a[TM], bb[TN];
            #pragma unroll
            for (int i = 0; i < TM; i++) a[i] = As[kk][ty * TM + i];
            #pragma unroll
            for (int j = 0; j < TN; j++) bb[j] = Bs[kk][tx * TN + j];
            #pragma unroll
            for (int i = 0; i < TM; i++)
                #pragma unroll
                for (int j = 0; j < TN; j++) acc[i][j] += a[i] * bb[j];
        }
        __syncthreads();
    }
    #pragma unroll
    for (int i = 0; i < TM; i++)
        #pragma unroll
        for (int j = 0; j < TN; j++) {
            int m = row0 + ty * TM + i, n = col0 + tx * TN + j;
            if (m < M && n < N) {
                float v = acc[i][j] + (bias ? bias[n] : 0.0f);
                if (act == 1) v = tanhf(v);
                C[(size_t)m * N + n] = v;
            }
        }
}

// 3-pass softmax: max; exp-write+sum (single __expf per element); scale.
__global__ void softmax_beta_kernel() {
    __shared__ float red[256];
    int row = blockIdx.x, tid = threadIdx.x;
    float4* p = (float4*)(g_beta + (size_t)row * V_);
    const int n4 = V_ / 4;  // 2500
    float mx = -1e30f;
    for (int v = tid; v < n4; v += 256) {
        float4 a = p[v];
        mx = fmaxf(mx, fmaxf(fmaxf(a.x, a.y), fmaxf(a.z, a.w)));
    }
    red[tid] = mx; __syncthreads();
    for (int s = 128; s > 0; s >>= 1) { if (tid < s) red[tid] = fmaxf(red[tid], red[tid + s]); __syncthreads(); }
    mx = red[0]; __syncthreads();
    float sum = 0.0f;
    for (int v = tid; v < n4; v += 256) {
        float4 a = p[v];
        a.x = __expf(a.x - mx);
        a.y = __expf(a.y - mx);
        a.z = __expf(a.z - mx);
        a.w = __expf(a.w - mx);
        sum += a.x + a.y + a.z + a.w;
        p[v] = a;
    }
    red[tid] = sum; __syncthreads();
    for (int s = 128; s > 0; s >>= 1) { if (tid < s) red[tid] += red[tid + s]; __syncthreads(); }
    float inv = 1.0f / red[0];
    for (int v = tid; v < n4; v += 256) {
        float4 a = p[v];
        a.x *= inv; a.y *= inv; a.z *= inv; a.w *= inv;
        p[v] = a;
    }
}

__global__ void theta_kl_kernel(const int* __restrict__ times) {
    __shared__ float red[64];
    int b = blockIdx.x, tid = threadIdx.x;  // 64 threads
    float mu = (tid < K_) ? g_muth[b * K_ + tid] : -1e30f;
    red[tid] = mu; __syncthreads();
    for (int s = 32; s > 0; s >>= 1) { if (tid < s) red[tid] = fmaxf(red[tid], red[tid + s]); __syncthreads(); }
    float mx = red[0]; __syncthreads();
    float e = (tid < K_) ? expf(mu - mx) : 0.0f;
    red[tid] = e; __syncthreads();
    for (int s = 32; s > 0; s >>= 1) { if (tid < s) red[tid] += red[tid + s]; __syncthreads(); }
    float sum = red[0]; __syncthreads();
    if (tid < K_) g_theta[b * K_ + tid] = e / sum;
    float kl = 0.0f;
    if (tid < K_) {
        float ls = g_lsth[b * K_ + tid];
        float et = g_etas[times[b] * K_ + tid];
        float d = mu - et;
        kl = 0.5f * ((expf(ls) + d * d) / (1.0f + 1e-6f) - 1.0f - ls);
    }
    red[tid] = kl; __syncthreads();
    for (int s = 32; s > 0; s >>= 1) { if (tid < s) red[tid] += red[tid + s]; __syncthreads(); }
    if (tid == 0) atomicAdd(&g_stats[3], red[0]);
}

#define NLL_SPLIT 5
__global__ void nll_kernel(const float* __restrict__ bows, const int* __restrict__ times) {
    __shared__ float th[K_];
    __shared__ float sh[256];
    int b = blockIdx.x, tid = threadIdx.x;
    const int n4 = V_ / 4;
    const int c4 = n4 / NLL_SPLIT;
    int v0 = blockIdx.y * c4;
    if (tid < K_) th[tid] = g_theta[b * K_ + tid];
    __syncthreads();
    int tb = times[b];
    const float* beta = g_beta + (size_t)tb * K_ * V_;
    const float4* bw4 = (const float4*)(bows + (size_t)b * V_);
    float acc = 0.0f;
    for (int v = v0 + tid; v < v0 + c4; v += 256) {
        float4 mix = make_float4(1e-6f, 1e-6f, 1e-6f, 1e-6f);
        #pragma unroll 5
        for (int k = 0; k < K_; k++) {
            float t = th[k];
            float4 bb = ((const float4*)(beta + (size_t)k * V_))[v];
            mix.x += t * bb.x; mix.y += t * bb.y; mix.z += t * bb.z; mix.w += t * bb.w;
        }
        float4 w = bw4[v];
        acc -= __logf(mix.x) * w.x + __logf(mix.y) * w.y
             + __logf(mix.z) * w.z + __logf(mix.w) * w.w;
    }
    float tot = blockReduceSum256(acc, sh);
    if (tid == 0) atomicAdd(&g_stats[2], tot);
}

__global__ void finalize_kernel(const int* __restrict__ num_docs, float* __restrict__ out,
                                int out_size) {
    float coeff = (float)num_docs[0] / (float)B_;
    float nll_s = g_stats[2] * coeff;
    float klth = g_stats[3] * coeff;
    float nelbo = nll_s + g_stats[0] + g_stats[1] + klth;
    if (out_size > 0) out[0] = nelbo;
    if (out_size > 1) out[1] = nll_s;
    if (out_size > 2) out[2] = g_stats[0];
    if (out_size > 3) out[3] = g_stats[1];
    if (out_size > 4) out[4] = klth;
}

// ---------------- launch ------------------------------------------------------
extern "C" void kernel_launch(void* const* d_in, const int* in_sizes, int n_in,
                              void* d_out, int out_size) {
    const float* mu_q_alpha   = (const float*)d_in[0];
    const float* lsig_q_alpha = (const float*)d_in[1];
    const float* src_logcov   = (const float*)d_in[2];
    const float* rho_W        = (const float*)d_in[3];
    const float* theta_W1     = (const float*)d_in[4];
    const float* theta_b1     = (const float*)d_in[5];
    const float* theta_W2     = (const float*)d_in[6];
    const float* theta_b2     = (const float*)d_in[7];
    const float* mu_theta_W   = (const float*)d_in[8];
    const float* mu_theta_b   = (const float*)d_in[9];
    const float* ls_theta_W   = (const float*)d_in[10];
    const float* ls_theta_b   = (const float*)d_in[11];
    const float* eta_map_W    = (const float*)d_in[12];
    const float* eta_map_b    = (const float*)d_in[13];
    const float* lstm_Wih     = (const float*)d_in[14];
    const float* lstm_Whh     = (const float*)d_in[15];
    const float* lstm_bih     = (const float*)d_in[16];
    const float* lstm_bhh     = (const float*)d_in[17];
    const float* mu_eta_W     = (const float*)d_in[18];
    const float* mu_eta_b     = (const float*)d_in[19];
    const float* ls_eta_W     = (const float*)d_in[20];
    const float* ls_eta_b     = (const float*)d_in[21];
    const float* bows         = (const float*)d_in[22];
    const float* norm_bows    = (const float*)d_in[23];
    const float* rnn_inp      = (const float*)d_in[24];
    const int*   times        = (const int*)d_in[25];
    const int*   num_docs     = (const int*)d_in[26];
    float* out = (float*)d_out;

    float *d_A1, *d_h1, *d_h2, *d_muth, *d_lsth, *d_alpha0, *d_beta, *d_xemb, *d_Gx, *d_biasc;
    cudaGetSymbolAddress((void**)&d_A1, g_A1);
    cudaGetSymbolAddress((void**)&d_h1, g_h1);
    cudaGetSymbolAddress((void**)&d_h2, g_h2);
    cudaGetSymbolAddress((void**)&d_muth, g_muth);
    cudaGetSymbolAddress((void**)&d_lsth, g_lsth);
    cudaGetSymbolAddress((void**)&d_alpha0, g_alpha0);
    cudaGetSymbolAddress((void**)&d_beta, g_beta);
    cudaGetSymbolAddress((void**)&d_xemb, g_xemb);
    cudaGetSymbolAddress((void**)&d_Gx, g_Gx);
    cudaGetSymbolAddress((void**)&d_biasc, g_biasc);

    init_kernel<<<1, 32>>>();
    prep_prior_kernel<<<1, 1>>>(src_logcov);
    {
        int n = NB_ * EH4_ * ROWS_;  // 40000, covers all prep work
        prep_lstm_kernel<<<(n + 255) / 256, 256>>>(lstm_Whh, mu_eta_W, ls_eta_W,
                                                   lstm_bih, lstm_bhh);
    }
    {
        int n = K_ * T_ * R_;
        kl_alpha_kernel<<<(n + 255) / 256, 256>>>(mu_q_alpha, lsig_q_alpha);
    }
    {
        int warps = T_ * EH_;
        xemb_kernel<<<(warps * 32 + 255) / 256, 256>>>(rnn_inp, eta_map_W, eta_map_b);
    }
    // Gx[t][gate] = xemb[t] @ Wih^T + (bih + bhh)
    {
        dim3 grid((GATE_ + 31) / 32, (T_ + 31) / 32);
        sgemm_tn<32, 32, 32, 2, 2><<<grid, 256>>>(d_xemb, lstm_Wih, d_biasc, d_Gx,
                                                  T_, GATE_, EH_, 0);
    }
    // multi-block LSTM + eta scan (9 resident blocks, per-step flag barrier)
    scan_kernel<<<NB_ + 1, 128>>>(mu_eta_b, ls_eta_b);
    {
        int n = B_ * VK_;
        build_A1_kernel<<<(n + 255) / 256, 256>>>(norm_bows, times);
    }
    // h1 = tanh(A1 @ W1^T + b1)  : (128 x 10050) x (800 x 10050)^T
    {
        dim3 grid((TH_ + 31) / 32, (B_ + 31) / 32);
        sgemm_tn<32, 32, 32, 2, 2><<<grid, 256>>>(d_A1, theta_W1, theta_b1, d_h1,
                                                  B_, TH_, VK_, 1);
    }
    // h2 = tanh(h1 @ W2^T + b2)
    {
        dim3 grid((TH_ + 31) / 32, (B_ + 31) / 32);
        sgemm_tn<32, 32, 32, 2, 2><<<grid, 256>>>(d_h1, theta_W2, theta_b2, d_h2,
                                                  B_, TH_, TH_, 1);
    }
    // mu_th / ls_th
    {
        dim3 grid((K_ + 31) / 32, (B_ + 31) / 32);
        sgemm_tn<32, 32, 32, 2, 2><<<grid, 256>>>(d_h2, mu_theta_W, mu_theta_b, d_muth,
                                                  B_, K_, TH_, 0);
        sgemm_tn<32, 32, 32, 2, 2><<<grid, 256>>>(d_h2, ls_theta_W, ls_theta_b, d_lsth,
                                                  B_, K_, TH_, 0);
    }
    {
        int n = T_ * K_ * R_;
        build_alpha0_kernel<<<(n + 255) / 256, 256>>>(mu_q_alpha);
    }
    // beta logits: (1250 x 128) x (10000 x 128)^T
    {
        dim3 grid((V_ + 63) / 64, (T_ * K_ + 63) / 64);
        sgemm_tn<64, 64, 16, 4, 4><<<grid, 256>>>(d_alpha0, rho_W, nullptr, d_beta,
                                                  T_ * K_, V_, R_, 0);
    }
    softmax_beta_kernel<<<T_ * K_, 256>>>();
    theta_kl_kernel<<<B_, 64>>>(times);
    {
        dim3 grid(B_, NLL_SPLIT);
        nll_kernel<<<grid, 256>>>(bows, times);
    }
    finalize_kernel<<<1, 1>>>(num_docs, out, out_size);
}

// round 8
// speedup vs baseline: 1.7311x; 1.7311x over previous
#include <cuda_runtime.h>
#include <math.h>
#include <stdint.h>

#define S_ 4
#define K_ 50
#define T_ 25
#define R_ 128
#define V_ 10000
#define TH_ 800
#define EH_ 200
#define B_ 128
#define VK_ (V_ + K_)
#define GATE_ (4 * EH_)    /* 800 */
#define INP_  (EH_ + K_)   /* 250 */
#define INP4_ 64           /* padded input quads */
#define EH4_  (EH_ / 4)    /* 50 */
#define NB_   8            /* gate blocks in the scan */
#define UPB_  (EH_ / NB_)  /* 25 units per gate block */
#define ROWS_ (4 * UPB_)   /* 100 gate rows per block */
#define LOG_DELTA (-5.2983173665480363f)

// ---------------- scratch --------------------------------------------------
__device__ float g_xemb[T_ * EH_];
__device__ float g_etas[T_ * K_];
__device__ float g_hs[T_ * EH_];
__device__ float g_A1[B_ * VK_];
__device__ float g_h1[B_ * TH_];
__device__ float g_h2[B_ * TH_];
__device__ float g_muth[B_ * K_];
__device__ float g_lsth[B_ * K_];
__device__ float g_theta[B_ * K_];
__device__ float g_alpha0[T_ * K_ * R_];
__device__ float g_beta[(size_t)T_ * K_ * V_];   // unnormalized exp after rowstat
__device__ float g_Z[T_ * K_];                   // row sums
__device__ float4 g_Wg4[NB_ * EH4_ * ROWS_];
__device__ float4 g_muWT4[INP4_ * K_];
__device__ float4 g_lsWT4[INP4_ * K_];
__device__ float g_biasc[GATE_];
__device__ float g_Gx[T_ * GATE_];
__device__ volatile int g_syncv;
// stats: 0=kl_alpha 1=kl_eta 2=nll 3=klth 4=ld_p0 5..8=d_p0 9=ld_pt 10..13=d_pt
__device__ float g_stats[16];

// ---------------- helpers --------------------------------------------------
__device__ __forceinline__ float sigmoidf_(float x) { return 1.0f / (1.0f + expf(-x)); }

__device__ __forceinline__ float blockReduceSum256(float v, float* sh) {
    int tid = threadIdx.x;
    sh[tid] = v;
    __syncthreads();
    for (int s = blockDim.x >> 1; s > 0; s >>= 1) {
        if (tid < s) sh[tid] += sh[tid + s];
        __syncthreads();
    }
    return sh[0];
}

__device__ double logabsdet4(double M[4][4]) {
    double ld = 0.0;
    for (int i = 0; i < 4; i++) {
        int p = i; double best = fabs(M[i][i]);
        for (int r = i + 1; r < 4; r++)
            if (fabs(M[r][i]) > best) { best = fabs(M[r][i]); p = r; }
        if (p != i)
            for (int c = 0; c < 4; c++) { double t = M[i][c]; M[i][c] = M[p][c]; M[p][c] = t; }
        ld += log(fabs(M[i][i]));
        for (int r = i + 1; r < 4; r++) {
            double f = M[r][i] / M[i][i];
            for (int c = i; c < 4; c++) M[r][c] -= f * M[i][c];
        }
    }
    return ld;
}

// ---------------- prep ------------------------------------------------------
__global__ void prep_lstm_kernel(const float* __restrict__ Whh,
                                 const float* __restrict__ muW, const float* __restrict__ lsW,
                                 const float* __restrict__ bih, const float* __restrict__ bhh) {
    int idx = blockIdx.x * blockDim.x + threadIdx.x;
    if (idx == 0) { g_stats[0] = 0.0f; g_stats[2] = 0.0f; g_stats[3] = 0.0f; g_syncv = 0; }
    if (idx < NB_ * EH4_ * ROWS_) {
        int j  = idx / (EH4_ * ROWS_);
        int rem = idx % (EH4_ * ROWS_);
        int i4 = rem / ROWS_;
        int r  = rem % ROWS_;
        int q  = r / UPB_, ul = r % UPB_;
        int grow = q * EH_ + j * UPB_ + ul;
        const float* w = Whh + (size_t)grow * EH_ + 4 * i4;
        g_Wg4[idx] = make_float4(w[0], w[1], w[2], w[3]);
    }
    if (idx < INP4_ * K_) {
        int i4 = idx / K_, k = idx % K_;
        float4 m, l;
        float* mp = (float*)&m;
        float* lp = (float*)&l;
        for (int jj = 0; jj < 4; jj++) {
            int i = 4 * i4 + jj;
            mp[jj] = (i < INP_) ? muW[(size_t)k * INP_ + i] : 0.0f;
            lp[jj] = (i < INP_) ? lsW[(size_t)k * INP_ + i] : 0.0f;
        }
        g_muWT4[idx] = m;
        g_lsWT4[idx] = l;
    }
    if (idx < GATE_) g_biasc[idx] = bih[idx] + bhh[idx];
}

__global__ void prep_prior_kernel(const float* __restrict__ src) {
    double M0[4][4], Mt[4][4];
    for (int i = 0; i < 4; i++)
        for (int j = 0; j < 4; j++) {
            double v = (double)src[i * 4 + j];
            M0[i][j] = exp(v);
            Mt[i][j] = 0.005 * v;
        }
    for (int i = 0; i < 4; i++) {
        g_stats[5 + i]  = (float)M0[i][i];
        g_stats[10 + i] = (float)Mt[i][i];
    }
    g_stats[4] = (float)logabsdet4(M0);
    g_stats[9] = (float)logabsdet4(Mt);
}

// x_emb[t][e] = rnn_inp[t] . eta_map_W[e] + b[e]
__global__ void xemb_kernel(const float* __restrict__ rnn, const float* __restrict__ W,
                            const float* __restrict__ b) {
    int gw = (blockIdx.x * blockDim.x + threadIdx.x) >> 5;
    int lane = threadIdx.x & 31;
    if (gw >= T_ * EH_) return;
    int t = gw / EH_, e = gw % EH_;
    const float4* x = (const float4*)(rnn + (size_t)t * V_);
    const float4* w = (const float4*)(W + (size_t)e * V_);
    float acc = 0.0f;
    for (int v = lane; v < V_ / 4; v += 32) {
        float4 a = x[v], c = w[v];
        acc += a.x * c.x + a.y * c.y + a.z * c.z + a.w * c.w;
    }
    for (int o = 16; o > 0; o >>= 1) acc += __shfl_down_sync(0xffffffffu, acc, o);
    if (lane == 0) g_xemb[t * EH_ + e] = acc + b[e];
}

// ---------------- split-K SGEMM: C[M,N] (+)= A[M,Kd] * B[N,Kd]^T ------------
template <int BM, int BN, int BK, int TM, int TN, bool ATOMIC>
__global__ void sgemm_sk(const float* __restrict__ A, const float* __restrict__ Bm,
                         float* __restrict__ C, int M, int N, int Kd, int kchunk) {
    constexpr int TX = BN / TN;
    constexpr int TY = BM / TM;
    constexpr int NT = TX * TY;
    constexpr int PAD = 4;
    __shared__ float As[BK][BM + PAD];
    __shared__ float Bs[BK][BN + PAD];
    int tid = threadIdx.x;
    int tx = tid % TX, ty = tid / TX;
    int row0 = blockIdx.y * BM, col0 = blockIdx.x * BN;
    int k_begin = blockIdx.z * kchunk;
    int k_end = k_begin + kchunk;
    if (k_end > Kd) k_end = Kd;
    float acc[TM][TN];
    #pragma unroll
    for (int i = 0; i < TM; i++)
        #pragma unroll
        for (int j = 0; j < TN; j++) acc[i][j] = 0.0f;
    for (int k0 = k_begin; k0 < k_end; k0 += BK) {
        #pragma unroll
        for (int i = tid; i < BM * BK; i += NT) {
            int m = i / BK, kk = i % BK;
            int gm = row0 + m, gk = k0 + kk;
            As[kk][m] = (gm < M && gk < k_end) ? A[(size_t)gm * Kd + gk] : 0.0f;
        }
        #pragma unroll
        for (int i = tid; i < BN * BK; i += NT) {
            int n = i / BK, kk = i % BK;
            int gn = col0 + n, gk = k0 + kk;
            Bs[kk][n] = (gn < N && gk < k_end) ? Bm[(size_t)gn * Kd + gk] : 0.0f;
        }
        __syncthreads();
        #pragma unroll
        for (int kk = 0; kk < BK; kk++) {
            float a[TM], bb[TN];
            #pragma unroll
            for (int i = 0; i < TM; i++) a[i] = As[kk][ty * TM + i];
            #pragma unroll
            for (int j = 0; j < TN; j++) bb[j] = Bs[kk][tx * TN + j];
            #pragma unroll
            for (int i = 0; i < TM; i++)
                #pragma unroll
                for (int j = 0; j < TN; j++) acc[i][j] += a[i] * bb[j];
        }
        __syncthreads();
    }
    #pragma unroll
    for (int i = 0; i < TM; i++)
        #pragma unroll
        for (int j = 0; j < TN; j++) {
            int m = row0 + ty * TM + i, n = col0 + tx * TN + j;
            if (m < M && n < N) {
                if (ATOMIC) atomicAdd(&C[(size_t)m * N + n], acc[i][j]);
                else C[(size_t)m * N + n] = acc[i][j];
            }
        }
}

__global__ void zero_acc_kernel() {
    int idx = blockIdx.x * blockDim.x + threadIdx.x;
    if (idx < B_ * TH_) { g_h1[idx] = 0.0f; g_h2[idx] = 0.0f; }
    if (idx < B_ * K_)  { g_muth[idx] = 0.0f; g_lsth[idx] = 0.0f; }
}

__global__ void bias_tanh_kernel(float* __restrict__ C, const float* __restrict__ bias, int n) {
    int idx = blockIdx.x * blockDim.x + threadIdx.x;
    if (idx < B_ * n) C[idx] = tanhf(C[idx] + bias[idx % n]);
}

// ---------------- scan (9 blocks: 8 gate + 1 eta) ---------------------------
__global__ void scan_kernel(const float* __restrict__ mub, const float* __restrict__ lsb) {
    int j = blockIdx.x;
    int tid = threadIdx.x;
    if (j < NB_) {
        __shared__ float hvec[EH_];
        __shared__ float gloc[ROWS_];
        __shared__ float cst[UPB_];
        if (tid < UPB_) cst[tid] = 0.0f;
        __syncthreads();
        for (int t = 0; t < T_; t++) {
            if (t > 0) {
                if (tid == 0) { while (g_syncv < NB_ * t) { } }
                __syncthreads();
                __threadfence();
                for (int i = tid; i < EH_; i += 128)
                    hvec[i] = __ldcg(&g_hs[(t - 1) * EH_ + i]);
                __syncthreads();
            }
            if (tid < ROWS_) {
                float acc = 0.0f;
                if (t > 0) {
                    const float4* w = g_Wg4 + (size_t)j * EH4_ * ROWS_ + tid;
                    float a0 = 0, a1 = 0, a2 = 0, a3 = 0;
                    #pragma unroll 10
                    for (int i4 = 0; i4 < EH4_; i4++) {
                        float4 q = w[i4 * ROWS_];
                        a0 += q.x * hvec[4 * i4 + 0];
                        a1 += q.y * hvec[4 * i4 + 1];
                        a2 += q.z * hvec[4 * i4 + 2];
                        a3 += q.w * hvec[4 * i4 + 3];
                    }
                    acc = (a0 + a1) + (a2 + a3);
                }
                int q = tid / UPB_, ul = tid % UPB_;
                int grow = q * EH_ + j * UPB_ + ul;
                gloc[tid] = acc + g_Gx[t * GATE_ + grow] + g_biasc[grow];
            }
            __syncthreads();
            if (tid < UPB_) {
                float ig = sigmoidf_(gloc[tid]);
                float fg = sigmoidf_(gloc[UPB_ + tid]);
                float gg = tanhf(gloc[2 * UPB_ + tid]);
                float og = sigmoidf_(gloc[3 * UPB_ + tid]);
                float c = fg * cst[tid] + ig * gg;
                cst[tid] = c;
                g_hs[t * EH_ + j * UPB_ + tid] = og * tanhf(c);
            }
            __threadfence();
            __syncthreads();
            if (tid == 0) atomicAdd((int*)&g_syncv, 1);
        }
    } else {
        __shared__ float inp[4 * INP4_];
        __shared__ float newmu[K_], klk[K_];
        for (int i = tid; i < 4 * INP4_; i += 128) inp[i] = 0.0f;
        __syncthreads();
        float klacc = 0.0f;
        for (int t = 0; t < T_; t++) {
            if (tid == 0) { while (g_syncv < NB_ * (t + 1)) { } }
            __syncthreads();
            __threadfence();
            for (int i = tid; i < EH_; i += 128)
                inp[i] = __ldcg(&g_hs[t * EH_ + i]);
            __syncthreads();
            if (tid < K_) {
                float m0 = 0, m1 = 0, l0 = 0, l1 = 0;
                const float4* wm = g_muWT4 + tid;
                const float4* wl = g_lsWT4 + tid;
                #pragma unroll 8
                for (int i4 = 0; i4 < INP4_; i4++) {
                    float4 a = wm[i4 * K_];
                    float4 bq = wl[i4 * K_];
                    float x0 = inp[4 * i4 + 0], x1 = inp[4 * i4 + 1];
                    float x2 = inp[4 * i4 + 2], x3 = inp[4 * i4 + 3];
                    m0 += a.x * x0 + a.y * x1;
                    m1 += a.z * x2 + a.w * x3;
                    l0 += bq.x * x0 + bq.y * x1;
                    l1 += bq.z * x2 + bq.w * x3;
                }
                float m = mub[tid] + m0 + m1;
                float l = lsb[tid] + l0 + l1;
                float pls = (t == 0) ? 0.0f : LOG_DELTA;
                float denom = expf(pls) + 1e-6f;
                float ep = inp[EH_ + tid];
                float d = m - ep;
                klk[tid] = 0.5f * ((expf(l) + d * d) / denom - 1.0f + pls - l);
                newmu[tid] = m;
                g_etas[t * K_ + tid] = m;
            }
            __syncthreads();
            if (tid < K_) inp[EH_ + tid] = newmu[tid];
            if (tid == 0) { float s = 0.0f; for (int k = 0; k < K_; k++) s += klk[k]; klacc += s; }
            __syncthreads();
        }
        if (tid == 0) g_stats[1] = klacc;
    }
}

// ---------------- rest ------------------------------------------------------
__global__ void kl_alpha_kernel(const float* __restrict__ mu, const float* __restrict__ lsig) {
    __shared__ float sh[256];
    int idx = blockIdx.x * blockDim.x + threadIdx.x;
    float val = 0.0f;
    if (idx < K_ * T_ * R_) {
        int r = idx % R_;
        int t = (idx / R_) % T_;
        int k = idx / (R_ * T_);
        float ldp = (t == 0) ? g_stats[4] : g_stats[9];
        const float* dp = (t == 0) ? &g_stats[5] : &g_stats[10];
        float acc = -ldp - (float)S_;
        for (int s = 0; s < S_; s++) {
            size_t off = ((size_t)(s * K_ + k) * T_ + t) * R_ + r;
            float lsv = lsig[off];
            float invq = expf(-lsv);
            float m = mu[off];
            float dmu = (t == 0) ? m : (m - mu[off - R_]);
            acc += lsv + dp[s] * invq + dmu * dmu * invq;
        }
        val = acc;
    }
    float tot = blockReduceSum256(val, sh);
    if (threadIdx.x == 0) atomicAdd(&g_stats[0], tot);
}

__global__ void build_A1_kernel(const float* __restrict__ nb, const int* __restrict__ times) {
    int idx = blockIdx.x * blockDim.x + threadIdx.x;
    if (idx >= B_ * VK_) return;
    int b = idx / VK_, j = idx % VK_;
    g_A1[idx] = (j < V_) ? nb[(size_t)b * V_ + j] : g_etas[times[b] * K_ + (j - V_)];
}

__global__ void build_alpha0_kernel(const float* __restrict__ mu) {
    int idx = blockIdx.x * blockDim.x + threadIdx.x;
    if (idx >= T_ * K_ * R_) return;
    int r = idx % R_;
    int k = (idx / R_) % K_;
    int t = idx / (R_ * K_);
    g_alpha0[idx] = mu[((size_t)k * T_ + t) * R_ + r];
}

// per-row max + unnormalized exp (in place) + row sum Z
__global__ void beta_rowstat_kernel() {
    __shared__ float red[256];
    int row = blockIdx.x, tid = threadIdx.x;
    float4* p = (float4*)(g_beta + (size_t)row * V_);
    const int n4 = V_ / 4;
    float mx = -1e30f;
    for (int v = tid; v < n4; v += 256) {
        float4 a = p[v];
        mx = fmaxf(mx, fmaxf(fmaxf(a.x, a.y), fmaxf(a.z, a.w)));
    }
    red[tid] = mx; __syncthreads();
    for (int s = 128; s > 0; s >>= 1) { if (tid < s) red[tid] = fmaxf(red[tid], red[tid + s]); __syncthreads(); }
    mx = red[0]; __syncthreads();
    float sum = 0.0f;
    for (int v = tid; v < n4; v += 256) {
        float4 a = p[v];
        a.x = __expf(a.x - mx);
        a.y = __expf(a.y - mx);
        a.z = __expf(a.z - mx);
        a.w = __expf(a.w - mx);
        sum += a.x + a.y + a.z + a.w;
        p[v] = a;
    }
    red[tid] = sum; __syncthreads();
    for (int s = 128; s > 0; s >>= 1) { if (tid < s) red[tid] += red[tid + s]; __syncthreads(); }
    if (tid == 0) g_Z[row] = red[0];
}

__global__ void theta_kl_kernel(const int* __restrict__ times,
                                const float* __restrict__ mub, const float* __restrict__ lsb) {
    __shared__ float red[64];
    int b = blockIdx.x, tid = threadIdx.x;
    float mu = (tid < K_) ? (g_muth[b * K_ + tid] + mub[tid]) : -1e30f;
    red[tid] = mu; __syncthreads();
    for (int s = 32; s > 0; s >>= 1) { if (tid < s) red[tid] = fmaxf(red[tid], red[tid + s]); __syncthreads(); }
    float mx = red[0]; __syncthreads();
    float e = (tid < K_) ? expf(mu - mx) : 0.0f;
    red[tid] = e; __syncthreads();
    for (int s = 32; s > 0; s >>= 1) { if (tid < s) red[tid] += red[tid + s]; __syncthreads(); }
    float sum = red[0]; __syncthreads();
    if (tid < K_) g_theta[b * K_ + tid] = e / sum;
    float kl = 0.0f;
    if (tid < K_) {
        float ls = g_lsth[b * K_ + tid] + lsb[tid];
        float et = g_etas[times[b] * K_ + tid];
        float d = mu - et;
        kl = 0.5f * ((expf(ls) + d * d) / (1.0f + 1e-6f) - 1.0f - ls);
    }
    red[tid] = kl; __syncthreads();
    for (int s = 32; s > 0; s >>= 1) { if (tid < s) red[tid] += red[tid + s]; __syncthreads(); }
    if (tid == 0) atomicAdd(&g_stats[3], red[0]);
}

#define NLL_SPLIT 5
__global__ void nll_kernel(const float* __restrict__ bows, const int* __restrict__ times) {
    __shared__ float c[K_];     // theta_k / Z_row
    __shared__ float sh[256];
    int b = blockIdx.x, tid = threadIdx.x;
    const int n4 = V_ / 4;
    const int c4 = n4 / NLL_SPLIT;
    int v0 = blockIdx.y * c4;
    int tb = times[b];
    if (tid < K_) c[tid] = g_theta[b * K_ + tid] / g_Z[tb * K_ + tid];
    __syncthreads();
    const float* beta = g_beta + (size_t)tb * K_ * V_;
    const float4* bw4 = (const float4*)(bows + (size_t)b * V_);
    float acc = 0.0f;
    for (int v = v0 + tid; v < v0 + c4; v += 256) {
        float4 mix = make_float4(1e-6f, 1e-6f, 1e-6f, 1e-6f);
        #pragma unroll 5
        for (int k = 0; k < K_; k++) {
            float t = c[k];
            float4 bb = ((const float4*)(beta + (size_t)k * V_))[v];
            mix.x += t * bb.x; mix.y += t * bb.y; mix.z += t * bb.z; mix.w += t * bb.w;
        }
        float4 w = bw4[v];
        acc -= __logf(mix.x) * w.x + __logf(mix.y) * w.y
             + __logf(mix.z) * w.z + __logf(mix.w) * w.w;
    }
    float tot = blockReduceSum256(acc, sh);
    if (tid == 0) atomicAdd(&g_stats[2], tot);
}

__global__ void finalize_kernel(const int* __restrict__ num_docs, float* __restrict__ out,
                                int out_size) {
    float coeff = (float)num_docs[0] / (float)B_;
    float nll_s = g_stats[2] * coeff;
    float klth = g_stats[3] * coeff;
    float nelbo = nll_s + g_stats[0] + g_stats[1] + klth;
    if (out_size > 0) out[0] = nelbo;
    if (out_size > 1) out[1] = nll_s;
    if (out_size > 2) out[2] = g_stats[0];
    if (out_size > 3) out[3] = g_stats[1];
    if (out_size > 4) out[4] = klth;
}

// ---------------- launch ----------------------------------------------------
extern "C" void kernel_launch(void* const* d_in, const int* in_sizes, int n_in,
                              void* d_out, int out_size) {
    const float* mu_q_alpha   = (const float*)d_in[0];
    const float* lsig_q_alpha = (const float*)d_in[1];
    const float* src_logcov   = (const float*)d_in[2];
    const float* rho_W        = (const float*)d_in[3];
    const float* theta_W1     = (const float*)d_in[4];
    const float* theta_b1     = (const float*)d_in[5];
    const float* theta_W2     = (const float*)d_in[6];
    const float* theta_b2     = (const float*)d_in[7];
    const float* mu_theta_W   = (const float*)d_in[8];
    const float* mu_theta_b   = (const float*)d_in[9];
    const float* ls_theta_W   = (const float*)d_in[10];
    const float* ls_theta_b   = (const float*)d_in[11];
    const float* eta_map_W    = (const float*)d_in[12];
    const float* eta_map_b    = (const float*)d_in[13];
    const float* lstm_Wih     = (const float*)d_in[14];
    const float* lstm_Whh     = (const float*)d_in[15];
    const float* lstm_bih     = (const float*)d_in[16];
    const float* lstm_bhh     = (const float*)d_in[17];
    const float* mu_eta_W     = (const float*)d_in[18];
    const float* mu_eta_b     = (const float*)d_in[19];
    const float* ls_eta_W     = (const float*)d_in[20];
    const float* ls_eta_b     = (const float*)d_in[21];
    const float* bows         = (const float*)d_in[22];
    const float* norm_bows    = (const float*)d_in[23];
    const float* rnn_inp      = (const float*)d_in[24];
    const int*   times        = (const int*)d_in[25];
    const int*   num_docs     = (const int*)d_in[26];
    float* out = (float*)d_out;

    float *d_A1, *d_h1, *d_h2, *d_muth, *d_lsth, *d_alpha0, *d_beta, *d_xemb, *d_Gx;
    cudaGetSymbolAddress((void**)&d_A1, g_A1);
    cudaGetSymbolAddress((void**)&d_h1, g_h1);
    cudaGetSymbolAddress((void**)&d_h2, g_h2);
    cudaGetSymbolAddress((void**)&d_muth, g_muth);
    cudaGetSymbolAddress((void**)&d_lsth, g_lsth);
    cudaGetSymbolAddress((void**)&d_alpha0, g_alpha0);
    cudaGetSymbolAddress((void**)&d_beta, g_beta);
    cudaGetSymbolAddress((void**)&d_xemb, g_xemb);
    cudaGetSymbolAddress((void**)&d_Gx, g_Gx);

    // (1) prep (also zeroes stats accumulators + scan barrier)
    {
        int n = NB_ * EH4_ * ROWS_;
        prep_lstm_kernel<<<(n + 255) / 256, 256>>>(lstm_Whh, mu_eta_W, ls_eta_W,
                                                   lstm_bih, lstm_bhh);
    }
    // (2) x embedding
    {
        int warps = T_ * EH_;
        xemb_kernel<<<(warps * 32 + 255) / 256, 256>>>(rnn_inp, eta_map_W, eta_map_b);
    }
    // (3) Gx = xemb @ Wih^T (bias folded into scan)
    {
        dim3 grid((GATE_ + 31) / 32, (T_ + 31) / 32, 1);
        sgemm_sk<32, 32, 32, 2, 2, false><<<grid, 256>>>(d_xemb, lstm_Wih, d_Gx,
                                                         T_, GATE_, EH_, EH_);
    }
    // (4) scan  <-- profiler capture slot
    scan_kernel<<<NB_ + 1, 128>>>(mu_eta_b, ls_eta_b);
    // (5..) stats + theta chain + beta chain
    prep_prior_kernel<<<1, 1>>>(src_logcov);
    {
        int n = K_ * T_ * R_;
        kl_alpha_kernel<<<(n + 255) / 256, 256>>>(mu_q_alpha, lsig_q_alpha);
    }
    {
        int n = B_ * VK_;
        build_A1_kernel<<<(n + 255) / 256, 256>>>(norm_bows, times);
    }
    zero_acc_kernel<<<(B_ * TH_ + 255) / 256, 256>>>();
    // h1 raw = A1 @ W1^T  (split-K 16)
    {
        dim3 grid((TH_ + 127) / 128, (B_ + 127) / 128, 16);
        int kchunk = (VK_ + 15) / 16;
        sgemm_sk<128, 128, 8, 8, 8, true><<<grid, 256>>>(d_A1, theta_W1, d_h1,
                                                         B_, TH_, VK_, kchunk);
    }
    bias_tanh_kernel<<<(B_ * TH_ + 255) / 256, 256>>>(d_h1, theta_b1, TH_);
    // h2 raw = h1 @ W2^T  (split-K 8)
    {
        dim3 grid((TH_ + 127) / 128, (B_ + 127) / 128, 8);
        int kchunk = (TH_ + 7) / 8;
        sgemm_sk<128, 128, 8, 8, 8, true><<<grid, 256>>>(d_h1, theta_W2, d_h2,
                                                         B_, TH_, TH_, kchunk);
    }
    bias_tanh_kernel<<<(B_ * TH_ + 255) / 256, 256>>>(d_h2, theta_b2, TH_);
    // mu_th / ls_th raw (split-K 8; bias folded into theta_kl)
    {
        dim3 grid((K_ + 31) / 32, (B_ + 31) / 32, 8);
        int kchunk = (TH_ + 7) / 8;
        sgemm_sk<32, 32, 32, 2, 2, true><<<grid, 256>>>(d_h2, mu_theta_W, d_muth,
                                                        B_, K_, TH_, kchunk);
        sgemm_sk<32, 32, 32, 2, 2, true><<<grid, 256>>>(d_h2, ls_theta_W, d_lsth,
                                                        B_, K_, TH_, kchunk);
    }
    {
        int n = T_ * K_ * R_;
        build_alpha0_kernel<<<(n + 255) / 256, 256>>>(mu_q_alpha);
    }
    // beta logits: (1250 x 128) x (10000 x 128)^T
    {
        dim3 grid((V_ + 127) / 128, (T_ * K_ + 127) / 128, 1);
        sgemm_sk<128, 128, 8, 8, 8, false><<<grid, 256>>>(d_alpha0, rho_W, d_beta,
                                                          T_ * K_, V_, R_, R_);
    }
    beta_rowstat_kernel<<<T_ * K_, 256>>>();
    theta_kl_kernel<<<B_, 64>>>(times, mu_theta_b, ls_theta_b);
    {
        dim3 grid(B_, NLL_SPLIT);
        nll_kernel<<<grid, 256>>>(bows, times);
    }
    finalize_kernel<<<1, 1>>>(num_docs, out, out_size);
}